// round 13
// baseline (speedup 1.0000x reference)
#include <cuda_runtime.h>
#include <cuda_bf16.h>
#include <cstdint>

#define BATCH 8
#define CCH   256
#define CIQ   128
#define NSP   4096
#define NT64  (NSP / 64)

// fragment-interleaved scratch (allocation-free rule: __device__ globals)
static __device__ __align__(16) uint32_t g_Qf[(size_t)BATCH * NT64 * 4 * 8 * 32 * 4];
static __device__ __align__(16) uint32_t g_Kf[(size_t)BATCH * NT64 * 8 * 4 * 32 * 4];
static __device__ __align__(16) uint32_t g_Vf[(size_t)BATCH * NT64 * 4 * 16 * 32 * 4];
static __device__ float g_att[(size_t)BATCH * NSP * CCH];   // (B, N, C)

// ===========================================================================
__device__ __forceinline__ uint32_t smem_u32(const void* p) {
    uint32_t a;
    asm("{ .reg .u64 t; cvta.to.shared.u64 t, %1; cvt.u32.u64 %0, t; }"
        : "=r"(a) : "l"(p));
    return a;
}
__device__ __forceinline__ void mma_tf32(float* d, const uint32_t* a, const uint32_t* b) {
    asm volatile("mma.sync.aligned.m16n8k8.row.col.f32.tf32.tf32.f32 "
        "{%0,%1,%2,%3}, {%4,%5,%6,%7}, {%8,%9}, {%0,%1,%2,%3};"
        : "+f"(d[0]), "+f"(d[1]), "+f"(d[2]), "+f"(d[3])
        : "r"(a[0]), "r"(a[1]), "r"(a[2]), "r"(a[3]), "r"(b[0]), "r"(b[1]));
}
__device__ __forceinline__ void mma_bf16(float* d, const uint32_t* a, const uint32_t* b) {
    asm volatile("mma.sync.aligned.m16n8k16.row.col.f32.bf16.bf16.f32 "
        "{%0,%1,%2,%3}, {%4,%5,%6,%7}, {%8,%9}, {%0,%1,%2,%3};"
        : "+f"(d[0]), "+f"(d[1]), "+f"(d[2]), "+f"(d[3])
        : "r"(a[0]), "r"(a[1]), "r"(a[2]), "r"(a[3]), "r"(b[0]), "r"(b[1]));
}
__device__ __forceinline__ uint32_t pack_bf16(float lo, float hi) {
    uint32_t r;
    asm("cvt.rn.bf16x2.f32 %0, %1, %2;" : "=r"(r) : "f"(hi), "f"(lo));
    return r;
}
__device__ __forceinline__ void lds128(uint32_t* r, uint32_t a) {
    asm volatile("ld.shared.v4.b32 {%0,%1,%2,%3}, [%4];"
        : "=r"(r[0]), "=r"(r[1]), "=r"(r[2]), "=r"(r[3]) : "r"(a));
}
__device__ __forceinline__ void sts64(uint32_t a, uint32_t v0, uint32_t v1) {
    asm volatile("st.shared.v2.b32 [%0], {%1,%2};" :: "r"(a), "r"(v0), "r"(v1));
}
__device__ __forceinline__ void cpasync16(uint32_t s, const void* g) {
    asm volatile("cp.async.cg.shared.global [%0], [%1], 16;" :: "r"(s), "l"(g));
}
#define CP_COMMIT() asm volatile("cp.async.commit_group;" ::: "memory")
#define CP_WAIT1()  asm volatile("cp.async.wait_group 1;" ::: "memory")
#define CP_WAIT0()  asm volatile("cp.async.wait_group 0;" ::: "memory")

// attention smem: K 3x16KB, V 3x32KB, P 2x8KB, lsum 1KB (161.5 KB, 1 CTA/SM)
#define SMK(s)    ((s) * 16384)
#define SMV(s)    (49152 + (s) * 32768)
#define SMPB(pb)  (147456 + (pb) * 8192)
#define SML       163840
#define ATT_SMEM  (SML + 1024)

// ---------------------------------------------------------------------------
// flash attention (no-max softmax): bf16 QK^T + bf16 PV
// 512 threads / 16 warps (4 per SMSP) for LSU/tensor overlap; 3-stage rings
// ---------------------------------------------------------------------------
__device__ __forceinline__ void loadK(uint32_t sb, int st, const uint32_t* kg, int tid) {
    uint32_t kd = sb + SMK(st) + tid * 16;
    const char* kp = (const char*)kg + tid * 16;
    #pragma unroll
    for (int i = 0; i < 2; i++) cpasync16(kd + i * 8192, kp + i * 8192);
}
__device__ __forceinline__ void loadV(uint32_t sb, int st, const uint32_t* vg, int tid) {
    uint32_t vd = sb + SMV(st) + tid * 16;
    const char* vp = (const char*)vg + tid * 16;
    #pragma unroll
    for (int i = 0; i < 4; i++) cpasync16(vd + i * 8192, vp + i * 8192);
}

__global__ __launch_bounds__(512, 1) void rse_attn_mma()
{
    extern __shared__ char sm[];
    const uint32_t sb = smem_u32(sm);
    const int tid = threadIdx.x, w = tid >> 5, l = tid & 31;
    const int b = blockIdx.y, qt = blockIdx.x;
    const int q = l >> 2, r = l & 3;
    const int mt = w >> 2;     // m-tile 0..3 (both GEMMs)
    const int nq = w & 3;      // n-quarter 0..3 (both GEMMs)

    // Q fragments (bf16x2, m16n8k16 A), persistent in registers
    uint32_t Qb[8][4];
    {
        const uint32_t* qg = g_Qf + ((((size_t)b * NT64 + qt) * 4 + mt) * 8) * 128 + l * 4;
        #pragma unroll
        for (int kc2 = 0; kc2 < 8; kc2++) {
            uint4 v = *(const uint4*)(qg + (size_t)kc2 * 128);
            Qb[kc2][0] = v.x; Qb[kc2][1] = v.y; Qb[kc2][2] = v.z; Qb[kc2][3] = v.w;
        }
    }

    const uint32_t* kg = g_Kf + (size_t)b * NT64 * 4096;
    const uint32_t* vg = g_Vf + (size_t)b * NT64 * 8192;
    loadK(sb, 0, kg, tid);                               CP_COMMIT();
    loadK(sb, 1, kg + 4096, tid); loadV(sb, 0, vg, tid); CP_COMMIT();

    float O[8][4] = {};
    float rs0 = 0.f, rs1 = 0.f;

    for (int t = 0; t <= NT64; t++) {
        const int s = t & 1, pb = s ^ 1;
        const int ks = t % 3, vs = (t + 2) % 3;
        if (t < NT64) { CP_WAIT1(); } else { CP_WAIT0(); }
        __syncthreads();   // the only barrier per iteration

        if (t < NT64) {
            if (t + 2 < NT64) loadK(sb, (t + 2) % 3, kg + (size_t)(t + 2) * 4096, tid);
            if (t + 1 < NT64) loadV(sb, (t + 1) % 3, vg + (size_t)(t + 1) * 8192, tid);
            CP_COMMIT();
        }

        const bool g1 = (t < NT64), g2 = (t > 0);
        float c[2][4] = {};
        // ---- interleaved: GEMM1(t) [16 mma] + GEMM2(t-1) [32 mma] per warp
        #pragma unroll
        for (int u = 0; u < 4; u++) {
            if (g1) {
                #pragma unroll
                for (int kk = 0; kk < 2; kk++) {
                    const int kc2 = 2 * u + kk;
                    uint32_t bp[4];
                    lds128(bp, sb + SMK(ks) + (((kc2 * 4 + nq) * 32 + l) * 16));
                    mma_bf16(c[0], Qb[kc2], bp);
                    mma_bf16(c[1], Qb[kc2], bp + 2);
                }
            }
            if (g2) {
                uint32_t a0[4];
                lds128(a0, sb + SMPB(pb) + (((mt * 4 + u) * 32 + l) * 16));
                #pragma unroll
                for (int nti = 0; nti < 4; nti++) {
                    uint32_t vb[4];
                    lds128(vb, sb + SMV(vs) +
                           (((u * 16 + nq * 4 + nti) * 32 + l) * 16));
                    mma_bf16(O[2 * nti],     a0, vb);
                    mma_bf16(O[2 * nti + 1], a0, vb + 2);
                }
            }
        }
        if (g1) {
            // ---- exp + row-sum + pack bf16x2 -> P buf s (A-frag m16n8k16)
            // warp owns S rows [mt*16, +16), cols [nq*16, +16)
            #pragma unroll
            for (int nti = 0; nti < 2; nti++) {
                float p0 = __expf(c[nti][0]);
                float p1 = __expf(c[nti][1]);
                float p2 = __expf(c[nti][2]);
                float p3 = __expf(c[nti][3]);
                rs0 += p0 + p1; rs1 += p2 + p3;
                uint32_t u01 = pack_bf16(p0, p1);   // row q
                uint32_t u23 = pack_bf16(p2, p3);   // row q+8
                // P layout: mt*2048 + kc2(nq)*512 + q*64 + r*16 + nti*8
                uint32_t a = sb + SMPB(s) + mt * 2048 + nq * 512
                             + (q << 6) + (r << 4) + nti * 8;
                sts64(a, u01, u23);
            }
        }
    }

    // ---- row-sum reduce (quads) and combine across 4 column quarters
    rs0 += __shfl_xor_sync(~0u, rs0, 1); rs0 += __shfl_xor_sync(~0u, rs0, 2);
    rs1 += __shfl_xor_sync(~0u, rs1, 1); rs1 += __shfl_xor_sync(~0u, rs1, 2);
    float* lh = (float*)(sm + SML);
    lh[nq * 64 + mt * 16 + q]     = rs0;
    lh[nq * 64 + mt * 16 + q + 8] = rs1;
    __syncthreads();

    // ---- normalize + store att (B, N, C); warp: rows mt*16+q/+8, cols nq*64..
    float* ag = g_att + ((size_t)b * NSP + qt * 64) * CCH;
    {
        int r0 = mt * 16 + q;
        float inv0 = 1.f / (lh[r0] + lh[64 + r0] + lh[128 + r0] + lh[192 + r0]);
        int r1 = r0 + 8;
        float inv1 = 1.f / (lh[r1] + lh[64 + r1] + lh[128 + r1] + lh[192 + r1]);
        #pragma unroll
        for (int nt = 0; nt < 8; nt++) {
            int c0 = nq * 64 + nt * 8 + 2 * r;
            *(float2*)&ag[(size_t)r0 * CCH + c0] =
                make_float2(O[nt][0] * inv0, O[nt][1] * inv0);
            *(float2*)&ag[(size_t)r1 * CCH + c0] =
                make_float2(O[nt][2] * inv1, O[nt][3] * inv1);
        }
    }
}

// ---------------------------------------------------------------------------
// Projection GEMM, tf32 mma.sync, cp.async 2-stage pipeline.
// MODE 0: Q -> bf16 A-frag; MODE 1: K -> paired bf16 B-frag;
// MODE 2: V -> paired bf16 B-frag
// ---------------------------------------------------------------------------
template <int MODE>
__device__ __forceinline__ void proj_prefetch(uint32_t sb, int s, int c0,
                                              const float* W, const float* Xb,
                                              int i0, int n0, int tid) {
    #pragma unroll
    for (int j = 0; j < 2; j++) {
        int f = tid + j * 256;
        int i = f >> 3, c4 = f & 7;
        cpasync16(sb + s * 9216 + i * 144 + c4 * 16,
                  &W[(size_t)(i0 + i) * CCH + c0 + c4 * 4]);
    }
    #pragma unroll
    for (int j = 0; j < 2; j++) {
        int f = tid + j * 256;
        int c = f >> 4, n4 = f & 15;
        cpasync16(sb + 18432 + s * 9216 + c * 288 + n4 * 16,
                  &Xb[(size_t)(c0 + c) * NSP + n0 + n4 * 4]);
    }
}

template <int MODE>
__global__ __launch_bounds__(256) void rse_proj_mma(
    const float* __restrict__ W, const float* __restrict__ bias,
    const float* __restrict__ X, float* __restrict__ out)
{
    extern __shared__ float smf[];
    const uint32_t sb = smem_u32(smf);
    const int b  = blockIdx.z;
    const int i0 = blockIdx.y * 64;
    const int n0 = blockIdx.x * 64;
    const float* Xb = X + (size_t)b * CCH * NSP;
    const int tid = threadIdx.x, w = tid >> 5, l = tid & 31;
    const int q = l >> 2, r = l & 3;
    const int mtw = w >> 1, nhw = w & 1;

    proj_prefetch<MODE>(sb, 0, 0, W, Xb, i0, n0, tid);
    CP_COMMIT();

    float acc[4][4] = {};
    for (int ch = 0; ch < 8; ch++) {
        const int s = ch & 1;
        CP_WAIT0();
        __syncthreads();
        if (ch + 1 < 8) proj_prefetch<MODE>(sb, s ^ 1, (ch + 1) * 32, W, Xb, i0, n0, tid);
        CP_COMMIT();

        const float* Wp = smf + s * 2304;           // [i*36 + c]
        const float* Xp = smf + 4608 + s * 2304;    // [c*72 + n]
        #pragma unroll
        for (int kcl = 0; kcl < 4; kcl++) {
            const int kc8 = kcl * 8;
            uint32_t a[4];
            a[0] = __float_as_uint(Wp[(mtw * 16 + q    ) * 36 + kc8 + r    ]);
            a[1] = __float_as_uint(Wp[(mtw * 16 + q + 8) * 36 + kc8 + r    ]);
            a[2] = __float_as_uint(Wp[(mtw * 16 + q    ) * 36 + kc8 + r + 4]);
            a[3] = __float_as_uint(Wp[(mtw * 16 + q + 8) * 36 + kc8 + r + 4]);
            #pragma unroll
            for (int nt = 0; nt < 4; nt++) {
                const int nc = nhw * 32 + nt * 8 + q;
                uint32_t bb[2];
                bb[0] = __float_as_uint(Xp[(kc8 + r    ) * 72 + nc]);
                bb[1] = __float_as_uint(Xp[(kc8 + r + 4) * 72 + nc]);
                mma_tf32(acc[nt], a, bb);
            }
        }
        __syncthreads();
    }

    // bias + stage Ts[n-local][i-local] (aliases stage memory; mainloop done)
    float* Ts = smf;   // [n*68 + i]
    {
        const float blo = bias[i0 + mtw * 16 + q];
        const float bhi = bias[i0 + mtw * 16 + q + 8];
        #pragma unroll
        for (int nt = 0; nt < 4; nt++) {
            const int nb = nhw * 32 + nt * 8 + 2 * r;
            Ts[(nb    ) * 68 + mtw * 16 + q    ] = acc[nt][0] + blo;
            Ts[(nb + 1) * 68 + mtw * 16 + q    ] = acc[nt][1] + blo;
            Ts[(nb    ) * 68 + mtw * 16 + q + 8] = acc[nt][2] + bhi;
            Ts[(nb + 1) * 68 + mtw * 16 + q + 8] = acc[nt][3] + bhi;
        }
    }
    __syncthreads();

    const size_t nt64 = n0 >> 6;
    if (MODE == 0) {
        uint32_t* qout = (uint32_t*)out;
        #pragma unroll
        for (int k2 = 0; k2 < 2; k2++) {
            int p = w + 8 * k2;
            int mt = p >> 2, kcl = p & 3;
            int row = mt * 16 + q;
            int col = kcl * 16 + 2 * r;
            uint32_t u0 = pack_bf16(Ts[row * 68 + col],     Ts[row * 68 + col + 1]);
            uint32_t u1 = pack_bf16(Ts[(row + 8) * 68 + col], Ts[(row + 8) * 68 + col + 1]);
            uint32_t u2 = pack_bf16(Ts[row * 68 + col + 8], Ts[row * 68 + col + 9]);
            uint32_t u3 = pack_bf16(Ts[(row + 8) * 68 + col + 8], Ts[(row + 8) * 68 + col + 9]);
            size_t idx = ((((size_t)b * NT64 + nt64) * 4 + mt) * 8 + (i0 >> 4) + kcl) * 128
                         + l * 4;
            *(uint4*)&qout[idx] = make_uint4(u0, u1, u2, u3);
        }
    } else if (MODE == 1) {
        uint32_t* kout = (uint32_t*)out;
        #pragma unroll
        for (int k2 = 0; k2 < 4; k2++) {
            int p = w + 8 * k2;
            int ntl = p >> 2, kcl = p & 3;
            int n = ntl * 8 + q;
            int col = kcl * 16 + 2 * r;
            uint32_t u0 = pack_bf16(Ts[n * 68 + col],     Ts[n * 68 + col + 1]);
            uint32_t u1 = pack_bf16(Ts[n * 68 + col + 8], Ts[n * 68 + col + 9]);
            size_t idx = ((((size_t)b * NT64 + nt64) * 8 + (i0 >> 4) + kcl) * 4
                          + (ntl >> 1)) * 128 + l * 4 + (ntl & 1) * 2;
            *(uint2*)&kout[idx] = make_uint2(u0, u1);
        }
    } else {
        uint32_t* vout = (uint32_t*)out;
        #pragma unroll
        for (int k2 = 0; k2 < 8; k2++) {
            int pos = w + 8 * k2;
            int ntl = pos >> 3;
            int kc2 = (pos >> 1) & 3;
            int j   = pos & 1;
            int cc = ntl * 8 + q;
            int tt = kc2 * 16 + 2 * r + 8 * j;
            uint32_t v = pack_bf16(Ts[tt * 68 + cc], Ts[(tt + 1) * 68 + cc]);
            size_t idx = ((((size_t)b * NT64 + nt64) * 4 + kc2) * 16
                          + (i0 >> 4) + (ntl >> 1)) * 128
                         + l * 4 + (ntl & 1) * 2 + j;
            vout[idx] = v;
        }
    }
}

// ---------------------------------------------------------------------------
// Output conv, tf32 mma.sync, cp.async 2-stage pipeline; epilogue from regs.
// ---------------------------------------------------------------------------
__device__ __forceinline__ void oc_prefetch(uint32_t sb, int s, int c0,
                                            const float* wo, const float* ag,
                                            int o0, int n0, int tid) {
    #pragma unroll
    for (int j = 0; j < 2; j++) {
        int f = tid + j * 256;
        int i = f >> 3, c4 = f & 7;
        cpasync16(sb + s * 9216 + i * 144 + c4 * 16,
                  &wo[(size_t)(o0 + i) * CCH + c0 + c4 * 4]);
    }
    #pragma unroll
    for (int j = 0; j < 2; j++) {
        int f = tid + j * 256;
        int n = f >> 3, c4 = f & 7;
        cpasync16(sb + 18432 + s * 9216 + n * 144 + c4 * 16,
                  &ag[(size_t)(n0 + n) * CCH + c0 + c4 * 4]);
    }
}

__global__ __launch_bounds__(256) void rse_outconv_mma(
    const float* __restrict__ wo, const float* __restrict__ bo,
    const float* __restrict__ bng, const float* __restrict__ bnb,
    const float* __restrict__ bnm, const float* __restrict__ bnv,
    const float* __restrict__ gamma, const float* __restrict__ x_main,
    float* __restrict__ out)
{
    extern __shared__ float smf[];
    const uint32_t sb = smem_u32(smf);
    const int b  = blockIdx.z;
    const int o0 = blockIdx.y * 64;
    const int n0 = blockIdx.x * 64;
    const float* ag = g_att + (size_t)b * NSP * CCH;
    const int tid = threadIdx.x, w = tid >> 5, l = tid & 31;
    const int q = l >> 2, r = l & 3;
    const int mtw = w >> 1, nhw = w & 1;

    oc_prefetch(sb, 0, 0, wo, ag, o0, n0, tid);
    CP_COMMIT();

    float acc[4][4] = {};
    for (int ch = 0; ch < 8; ch++) {
        const int s = ch & 1;
        CP_WAIT0();
        __syncthreads();
        if (ch + 1 < 8) oc_prefetch(sb, s ^ 1, (ch + 1) * 32, wo, ag, o0, n0, tid);
        CP_COMMIT();

        const float* Wp = smf + s * 2304;           // [o*36 + c]
        const float* Ap = smf + 4608 + s * 2304;    // [n*36 + c]
        #pragma unroll
        for (int kcl = 0; kcl < 4; kcl++) {
            const int kc8 = kcl * 8;
            uint32_t a[4];
            a[0] = __float_as_uint(Wp[(mtw * 16 + q    ) * 36 + kc8 + r    ]);
            a[1] = __float_as_uint(Wp[(mtw * 16 + q + 8) * 36 + kc8 + r    ]);
            a[2] = __float_as_uint(Wp[(mtw * 16 + q    ) * 36 + kc8 + r + 4]);
            a[3] = __float_as_uint(Wp[(mtw * 16 + q + 8) * 36 + kc8 + r + 4]);
            #pragma unroll
            for (int nt = 0; nt < 4; nt++) {
                const int nc = nhw * 32 + nt * 8 + q;
                uint32_t bb[2];
                bb[0] = __float_as_uint(Ap[nc * 36 + kc8 + r    ]);
                bb[1] = __float_as_uint(Ap[nc * 36 + kc8 + r + 4]);
                mma_tf32(acc[nt], a, bb);
            }
        }
        __syncthreads();
    }
    const float g = gamma[0];
    const int olo = o0 + mtw * 16 + q, ohi = olo + 8;
    const float inv_lo = bng[olo] * rsqrtf(bnv[olo] + 1e-5f);
    const float bta_lo = bnb[olo] - bnm[olo] * inv_lo;
    const float bi_lo  = bo[olo];
    const float inv_hi = bng[ohi] * rsqrtf(bnv[ohi] + 1e-5f);
    const float bta_hi = bnb[ohi] - bnm[ohi] * inv_hi;
    const float bi_hi  = bo[ohi];
    const float* xm = x_main + (size_t)b * CCH * NSP;
    float* ob = out + (size_t)b * CCH * NSP;
    #pragma unroll
    for (int nt = 0; nt < 4; nt++) {
        const int n = n0 + nhw * 32 + nt * 8 + 2 * r;
        float2 rl = *(const float2*)&xm[(size_t)olo * NSP + n];
        float2 vl;
        vl.x = rl.x + g * fmaxf((acc[nt][0] + bi_lo) * inv_lo + bta_lo, 0.f);
        vl.y = rl.y + g * fmaxf((acc[nt][1] + bi_lo) * inv_lo + bta_lo, 0.f);
        *(float2*)&ob[(size_t)olo * NSP + n] = vl;
        float2 rh = *(const float2*)&xm[(size_t)ohi * NSP + n];
        float2 vh;
        vh.x = rh.x + g * fmaxf((acc[nt][2] + bi_hi) * inv_hi + bta_hi, 0.f);
        vh.y = rh.y + g * fmaxf((acc[nt][3] + bi_hi) * inv_hi + bta_hi, 0.f);
        *(float2*)&ob[(size_t)ohi * NSP + n] = vh;
    }
}

// ---------------------------------------------------------------------------
extern "C" void kernel_launch(void* const* d_in, const int* in_sizes, int n_in,
                              void* d_out, int out_size)
{
    const float* x_main  = (const float*)d_in[0];
    const float* x_guide = (const float*)d_in[1];
    const float* wq = (const float*)d_in[2];
    const float* bq = (const float*)d_in[3];
    const float* wk = (const float*)d_in[4];
    const float* bk = (const float*)d_in[5];
    const float* wv = (const float*)d_in[6];
    const float* bv = (const float*)d_in[7];
    const float* wo = (const float*)d_in[8];
    const float* bo = (const float*)d_in[9];
    const float* bng = (const float*)d_in[10];
    const float* bnb = (const float*)d_in[11];
    const float* bnm = (const float*)d_in[12];
    const float* bnv = (const float*)d_in[13];
    const float* gamma = (const float*)d_in[14];
    float* out = (float*)d_out;

    void *qf, *kf, *vf;
    cudaGetSymbolAddress(&qf, g_Qf);
    cudaGetSymbolAddress(&kf, g_Kf);
    cudaGetSymbolAddress(&vf, g_Vf);

    const int GEMM_SMEM = 36864;

    // projections -> bf16 fragment-interleaved layouts (cp.async pipelined)
    {
        dim3 gq(NSP / 64, CIQ / 64, BATCH);
        rse_proj_mma<0><<<gq, 256, GEMM_SMEM>>>(wq, bq, x_main,  (float*)qf);
        rse_proj_mma<1><<<gq, 256, GEMM_SMEM>>>(wk, bk, x_guide, (float*)kf);
        dim3 gv(NSP / 64, CCH / 64, BATCH);
        rse_proj_mma<2><<<gv, 256, GEMM_SMEM>>>(wv, bv, x_guide, (float*)vf);
    }
    // flash attention: bf16, 512 threads / 16 warps, 3-stage rings
    {
        cudaFuncSetAttribute(rse_attn_mma,
                             cudaFuncAttributeMaxDynamicSharedMemorySize, ATT_SMEM);
        dim3 grid(NSP / 64, BATCH);
        rse_attn_mma<<<grid, 512, ATT_SMEM>>>();
    }
    // output conv + BN + ReLU + residual (cp.async pipelined)
    {
        dim3 grid(NSP / 64, CCH / 64, BATCH);
        rse_outconv_mma<<<grid, 256, GEMM_SMEM>>>(wo, bo, bng, bnb, bnm, bnv,
                                                  gamma, x_main, out);
    }
}

// round 17
// speedup vs baseline: 1.1001x; 1.1001x over previous
#include <cuda_runtime.h>
#include <cuda_bf16.h>
#include <cstdint>

#define BATCH 8
#define CCH   256
#define CIQ   128
#define NSP   4096
#define NT64  (NSP / 64)

// fragment-interleaved scratch (allocation-free rule: __device__ globals)
static __device__ __align__(16) uint32_t g_Qf[(size_t)BATCH * NT64 * 4 * 8 * 32 * 4];
static __device__ __align__(16) uint32_t g_Kf[(size_t)BATCH * NT64 * 8 * 4 * 32 * 4];
static __device__ __align__(16) uint32_t g_Vf[(size_t)BATCH * NT64 * 4 * 16 * 32 * 4];
// Wo pre-packed bf16 A-frags: [ot(4)][mt(4)][kc2(16)][lane(32)][4]
static __device__ __align__(16) uint32_t g_Wof[4 * 4 * 16 * 32 * 4];

// ===========================================================================
__device__ __forceinline__ uint32_t smem_u32(const void* p) {
    uint32_t a;
    asm("{ .reg .u64 t; cvta.to.shared.u64 t, %1; cvt.u32.u64 %0, t; }"
        : "=r"(a) : "l"(p));
    return a;
}
__device__ __forceinline__ void mma_tf32(float* d, const uint32_t* a, const uint32_t* b) {
    asm volatile("mma.sync.aligned.m16n8k8.row.col.f32.tf32.tf32.f32 "
        "{%0,%1,%2,%3}, {%4,%5,%6,%7}, {%8,%9}, {%0,%1,%2,%3};"
        : "+f"(d[0]), "+f"(d[1]), "+f"(d[2]), "+f"(d[3])
        : "r"(a[0]), "r"(a[1]), "r"(a[2]), "r"(a[3]), "r"(b[0]), "r"(b[1]));
}
__device__ __forceinline__ void mma_bf16(float* d, const uint32_t* a, const uint32_t* b) {
    asm volatile("mma.sync.aligned.m16n8k16.row.col.f32.bf16.bf16.f32 "
        "{%0,%1,%2,%3}, {%4,%5,%6,%7}, {%8,%9}, {%0,%1,%2,%3};"
        : "+f"(d[0]), "+f"(d[1]), "+f"(d[2]), "+f"(d[3])
        : "r"(a[0]), "r"(a[1]), "r"(a[2]), "r"(a[3]), "r"(b[0]), "r"(b[1]));
}
__device__ __forceinline__ uint32_t pack_bf16(float lo, float hi) {
    uint32_t r;
    asm("cvt.rn.bf16x2.f32 %0, %1, %2;" : "=r"(r) : "f"(hi), "f"(lo));
    return r;
}
__device__ __forceinline__ void lds128(uint32_t* r, uint32_t a) {
    asm volatile("ld.shared.v4.b32 {%0,%1,%2,%3}, [%4];"
        : "=r"(r[0]), "=r"(r[1]), "=r"(r[2]), "=r"(r[3]) : "r"(a));
}
__device__ __forceinline__ void sts64(uint32_t a, uint32_t v0, uint32_t v1) {
    asm volatile("st.shared.v2.b32 [%0], {%1,%2};" :: "r"(a), "r"(v0), "r"(v1));
}
__device__ __forceinline__ void sts128(uint32_t a, uint32_t v0, uint32_t v1,
                                       uint32_t v2, uint32_t v3) {
    asm volatile("st.shared.v4.b32 [%0], {%1,%2,%3,%4};"
        :: "r"(a), "r"(v0), "r"(v1), "r"(v2), "r"(v3));
}
__device__ __forceinline__ void cpasync16(uint32_t s, const void* g) {
    asm volatile("cp.async.cg.shared.global [%0], [%1], 16;" :: "r"(s), "l"(g));
}
#define CP_COMMIT() asm volatile("cp.async.commit_group;" ::: "memory")
#define CP_WAIT1()  asm volatile("cp.async.wait_group 1;" ::: "memory")
#define CP_WAIT0()  asm volatile("cp.async.wait_group 0;" ::: "memory")

// attention smem: K 3x16KB @0, V 3x32KB @49152, P 2x8KB @147456 (ends 163840)
// post-mainloop reuse: Wof 128KB @0, AF 32KB @131072
// SML: lh 512B | inv 1KB | bet2 1KB
#define SMK(s)    ((s) * 16384)
#define SMV(s)    (49152 + (s) * 32768)
#define SMPB(pb)  (147456 + (pb) * 8192)
#define AFOFF     131072
#define SML       163840
#define ATT_SMEM  (SML + 512 + 2048)

// ---------------------------------------------------------------------------
// Wo -> bf16 A-frag prep (one-shot, 8192 threads)
// ---------------------------------------------------------------------------
__global__ void rse_wo_prep(const float* __restrict__ wo, uint32_t* __restrict__ wof)
{
    int gid = blockIdx.x * 512 + threadIdx.x;     // 16 blocks x 512
    int l = gid & 31, kc2 = (gid >> 5) & 15, mt = (gid >> 9) & 3, ot = gid >> 11;
    int q = l >> 2, r = l & 3;
    int o0 = ot * 64 + mt * 16 + q;
    int k0 = kc2 * 16 + 2 * r;
    uint32_t a0 = pack_bf16(wo[(size_t)o0 * CCH + k0],       wo[(size_t)o0 * CCH + k0 + 1]);
    uint32_t a1 = pack_bf16(wo[(size_t)(o0 + 8) * CCH + k0], wo[(size_t)(o0 + 8) * CCH + k0 + 1]);
    uint32_t a2 = pack_bf16(wo[(size_t)o0 * CCH + k0 + 8],   wo[(size_t)o0 * CCH + k0 + 9]);
    uint32_t a3 = pack_bf16(wo[(size_t)(o0 + 8) * CCH + k0 + 8], wo[(size_t)(o0 + 8) * CCH + k0 + 9]);
    *(uint4*)&wof[(size_t)gid * 4] = make_uint4(a0, a1, a2, a3);
}

// ---------------------------------------------------------------------------
// fused flash attention + output conv + BN + ReLU + residual
// mainloop = R12 (8 warps, 3-stage rings, 1 barrier/iter)
// ---------------------------------------------------------------------------
__device__ __forceinline__ void loadK(uint32_t sb, int st, const uint32_t* kg, int tid) {
    uint32_t kd = sb + SMK(st) + tid * 16;
    const char* kp = (const char*)kg + tid * 16;
    #pragma unroll
    for (int i = 0; i < 4; i++) cpasync16(kd + i * 4096, kp + i * 4096);
}
__device__ __forceinline__ void loadV(uint32_t sb, int st, const uint32_t* vg, int tid) {
    uint32_t vd = sb + SMV(st) + tid * 16;
    const char* vp = (const char*)vg + tid * 16;
    #pragma unroll
    for (int i = 0; i < 8; i++) cpasync16(vd + i * 4096, vp + i * 4096);
}

__global__ __launch_bounds__(256, 1) void rse_attn_fused(
    const float* __restrict__ bo,
    const float* __restrict__ bng, const float* __restrict__ bnb,
    const float* __restrict__ bnm, const float* __restrict__ bnv,
    const float* __restrict__ gamma, const float* __restrict__ x_main,
    float* __restrict__ out)
{
    extern __shared__ char sm[];
    const uint32_t sb = smem_u32(sm);
    const int tid = threadIdx.x, w = tid >> 5, l = tid & 31;
    const int b = blockIdx.y, qt = blockIdx.x;
    const int q = l >> 2, r = l & 3;
    const int mt1 = w >> 1, nh = w & 1;    // GEMM1 partition (4m x 2n)
    const int mh  = w >> 2, nq = w & 3;    // GEMM2 partition (2m x 4n)

    // BN tables: val = acc*inv[o] + bet2[o]; bet2 = bo*inv + bnb - bnm*inv
    float* sinv = (float*)(sm + SML + 512);
    float* sbet = (float*)(sm + SML + 1536);
    if (tid < 256) {
        float iv = bng[tid] * rsqrtf(bnv[tid] + 1e-5f);
        sinv[tid] = iv;
        sbet[tid] = bo[tid] * iv + bnb[tid] - bnm[tid] * iv;
    }

    // Q fragments (bf16x2, m16n8k16 A), persistent in registers
    uint32_t Qb[8][4];
    {
        const uint32_t* qg = g_Qf + ((((size_t)b * NT64 + qt) * 4 + mt1) * 8) * 128 + l * 4;
        #pragma unroll
        for (int kc2 = 0; kc2 < 8; kc2++) {
            uint4 v = *(const uint4*)(qg + (size_t)kc2 * 128);
            Qb[kc2][0] = v.x; Qb[kc2][1] = v.y; Qb[kc2][2] = v.z; Qb[kc2][3] = v.w;
        }
    }

    const uint32_t* kg = g_Kf + (size_t)b * NT64 * 4096;
    const uint32_t* vg = g_Vf + (size_t)b * NT64 * 8192;
    loadK(sb, 0, kg, tid);                               CP_COMMIT();
    loadK(sb, 1, kg + 4096, tid); loadV(sb, 0, vg, tid); CP_COMMIT();

    float O[2][8][4] = {};
    float rs0 = 0.f, rs1 = 0.f;

    for (int t = 0; t <= NT64; t++) {
        const int s = t & 1, pb = s ^ 1;
        const int ks = t % 3, vs = (t + 2) % 3;
        if (t < NT64) { CP_WAIT1(); } else { CP_WAIT0(); }
        __syncthreads();

        if (t < NT64) {
            if (t + 2 < NT64) loadK(sb, (t + 2) % 3, kg + (size_t)(t + 2) * 4096, tid);
            if (t + 1 < NT64) loadV(sb, (t + 1) % 3, vg + (size_t)(t + 1) * 8192, tid);
            CP_COMMIT();
        }

        const bool g1 = (t < NT64), g2 = (t > 0);
        float c[4][4] = {};
        #pragma unroll
        for (int u = 0; u < 4; u++) {
            if (g1) {
                #pragma unroll
                for (int kk = 0; kk < 2; kk++) {
                    const int kc2 = 2 * u + kk;
                    #pragma unroll
                    for (int nti = 0; nti < 2; nti++) {
                        uint32_t bp[4];
                        lds128(bp, sb + SMK(ks) +
                               (((kc2 * 4 + nh * 2 + nti) * 32 + l) * 16));
                        mma_bf16(c[2 * nti],     Qb[kc2], bp);
                        mma_bf16(c[2 * nti + 1], Qb[kc2], bp + 2);
                    }
                }
            }
            if (g2) {
                uint32_t a0[4], a1[4];
                lds128(a0, sb + SMPB(pb) + ((((2 * mh)     * 4 + u) * 32 + l) * 16));
                lds128(a1, sb + SMPB(pb) + ((((2 * mh + 1) * 4 + u) * 32 + l) * 16));
                #pragma unroll
                for (int nti = 0; nti < 4; nti++) {
                    uint32_t vb[4];
                    lds128(vb, sb + SMV(vs) +
                           (((u * 16 + nq * 4 + nti) * 32 + l) * 16));
                    mma_bf16(O[0][2 * nti],     a0, vb);
                    mma_bf16(O[0][2 * nti + 1], a0, vb + 2);
                    mma_bf16(O[1][2 * nti],     a1, vb);
                    mma_bf16(O[1][2 * nti + 1], a1, vb + 2);
                }
            }
        }
        if (g1) {
            #pragma unroll
            for (int nt = 0; nt < 4; nt++) {
                float p0 = __expf(c[nt][0]);
                float p1 = __expf(c[nt][1]);
                float p2 = __expf(c[nt][2]);
                float p3 = __expf(c[nt][3]);
                rs0 += p0 + p1; rs1 += p2 + p3;
                uint32_t u01 = pack_bf16(p0, p1);
                uint32_t u23 = pack_bf16(p2, p3);
                int pr = nh * 16 + nt * 4 + r;
                int kc2 = pr >> 3, ps = pr & 7;
                int jb = (ps >= 4) ? 2 : 0, rp = ps & 3;
                uint32_t a = sb + SMPB(s) +
                    (((kc2 * 32 + (q << 2) + rp) * 4 + jb) * 4) + mt1 * 2048;
                sts64(a, u01, u23);
            }
        }
    }

    // ---- row-sum reduce + combine column halves
    rs0 += __shfl_xor_sync(~0u, rs0, 1); rs0 += __shfl_xor_sync(~0u, rs0, 2);
    rs1 += __shfl_xor_sync(~0u, rs1, 1); rs1 += __shfl_xor_sync(~0u, rs1, 2);
    float* lh = (float*)(sm + SML);
    lh[nh * 64 + mt1 * 16 + q]     = rs0;
    lh[nh * 64 + mt1 * 16 + q + 8] = rs1;
    __syncthreads();   // mainloop smem (K/V/P) now dead

    // ---- stage Wo A-frags (128KB) into smem @0 over dead K/V rings
    {
        const char* wsrc = (const char*)g_Wof + tid * 16;
        uint32_t wd = sb + tid * 16;
        #pragma unroll
        for (int i = 0; i < 32; i++) cpasync16(wd + i * 4096, wsrc + i * 4096);
        CP_COMMIT();
    }

    // ---- normalize + pack O into att B-frags @AFOFF
    #pragma unroll
    for (int m = 0; m < 2; m++) {
        int r0 = (2 * mh + m) * 16 + q;
        float inv0 = 1.f / (lh[r0]     + lh[64 + r0]);
        float inv1 = 1.f / (lh[r0 + 8] + lh[64 + r0 + 8]);
        #pragma unroll
        for (int k = 0; k < 4; k++) {
            uint32_t u0e = pack_bf16(O[m][2*k][0]   * inv0, O[m][2*k][1]   * inv0);
            uint32_t u1e = pack_bf16(O[m][2*k+1][0] * inv0, O[m][2*k+1][1] * inv0);
            uint32_t u0o = pack_bf16(O[m][2*k][2]   * inv1, O[m][2*k][3]   * inv1);
            uint32_t u1o = pack_bf16(O[m][2*k+1][2] * inv1, O[m][2*k+1][3] * inv1);
            uint32_t a = sb + AFOFF +
                ((((nq * 4 + k) * 4 + (2 * mh + m)) * 32 + l) * 16);
            sts128(a, u0e, u1e, u0o, u1o);
        }
    }
    CP_WAIT0();
    __syncthreads();

    // ---- fused GEMM: out[o][n] = Wo . att^T, + BN + ReLU + residual
    const int ow = w >> 2, nw = w & 3;   // 2 o-halves x 4 n-quarters
    const float g = gamma[0];
    const float* xm = x_main + (size_t)b * CCH * NSP;
    float* ob = out + (size_t)b * CCH * NSP;

    #pragma unroll
    for (int ot = 0; ot < 4; ot++) {
        float C[2][2][4] = {};
        #pragma unroll
        for (int kc2 = 0; kc2 < 16; kc2++) {
            uint32_t bb[4];
            lds128(bb, sb + AFOFF + (((kc2 * 4 + nw) * 32 + l) * 16));
            #pragma unroll
            for (int mt2 = 0; mt2 < 2; mt2++) {
                uint32_t a[4];
                lds128(a, sb + (((ot * 4 + ow * 2 + mt2) * 16 + kc2) * 512) + l * 16);
                mma_bf16(C[mt2][0], a, bb);
                mma_bf16(C[mt2][1], a, bb + 2);
            }
        }
        #pragma unroll
        for (int mt2 = 0; mt2 < 2; mt2++) {
            const int olo = ot * 64 + (ow * 2 + mt2) * 16 + q, ohi = olo + 8;
            const float ivl = sinv[olo], btl = sbet[olo];
            const float ivh = sinv[ohi], bth = sbet[ohi];
            #pragma unroll
            for (int j = 0; j < 2; j++) {
                const int n = qt * 64 + (2 * nw + j) * 8 + 2 * r;
                float2 rl = *(const float2*)&xm[(size_t)olo * NSP + n];
                float2 vl;
                vl.x = rl.x + g * fmaxf(C[mt2][j][0] * ivl + btl, 0.f);
                vl.y = rl.y + g * fmaxf(C[mt2][j][1] * ivl + btl, 0.f);
                *(float2*)&ob[(size_t)olo * NSP + n] = vl;
                float2 rh = *(const float2*)&xm[(size_t)ohi * NSP + n];
                float2 vh;
                vh.x = rh.x + g * fmaxf(C[mt2][j][2] * ivh + bth, 0.f);
                vh.y = rh.y + g * fmaxf(C[mt2][j][3] * ivh + bth, 0.f);
                *(float2*)&ob[(size_t)ohi * NSP + n] = vh;
            }
        }
    }
}

// ---------------------------------------------------------------------------
// Projection GEMM, tf32 mma.sync, cp.async 2-stage pipeline (R12, unchanged)
// ---------------------------------------------------------------------------
template <int MODE>
__device__ __forceinline__ void proj_prefetch(uint32_t sb, int s, int c0,
                                              const float* W, const float* Xb,
                                              int i0, int n0, int tid) {
    #pragma unroll
    for (int j = 0; j < 2; j++) {
        int f = tid + j * 256;
        int i = f >> 3, c4 = f & 7;
        cpasync16(sb + s * 9216 + i * 144 + c4 * 16,
                  &W[(size_t)(i0 + i) * CCH + c0 + c4 * 4]);
    }
    #pragma unroll
    for (int j = 0; j < 2; j++) {
        int f = tid + j * 256;
        int c = f >> 4, n4 = f & 15;
        cpasync16(sb + 18432 + s * 9216 + c * 288 + n4 * 16,
                  &Xb[(size_t)(c0 + c) * NSP + n0 + n4 * 4]);
    }
}

template <int MODE>
__global__ __launch_bounds__(256) void rse_proj_mma(
    const float* __restrict__ W, const float* __restrict__ bias,
    const float* __restrict__ X, float* __restrict__ out)
{
    extern __shared__ float smf[];
    const uint32_t sb = smem_u32(smf);
    const int b  = blockIdx.z;
    const int i0 = blockIdx.y * 64;
    const int n0 = blockIdx.x * 64;
    const float* Xb = X + (size_t)b * CCH * NSP;
    const int tid = threadIdx.x, w = tid >> 5, l = tid & 31;
    const int q = l >> 2, r = l & 3;
    const int mtw = w >> 1, nhw = w & 1;

    proj_prefetch<MODE>(sb, 0, 0, W, Xb, i0, n0, tid);
    CP_COMMIT();

    float acc[4][4] = {};
    for (int ch = 0; ch < 8; ch++) {
        const int s = ch & 1;
        CP_WAIT0();
        __syncthreads();
        if (ch + 1 < 8) proj_prefetch<MODE>(sb, s ^ 1, (ch + 1) * 32, W, Xb, i0, n0, tid);
        CP_COMMIT();

        const float* Wp = smf + s * 2304;           // [i*36 + c]
        const float* Xp = smf + 4608 + s * 2304;    // [c*72 + n]
        #pragma unroll
        for (int kcl = 0; kcl < 4; kcl++) {
            const int kc8 = kcl * 8;
            uint32_t a[4];
            a[0] = __float_as_uint(Wp[(mtw * 16 + q    ) * 36 + kc8 + r    ]);
            a[1] = __float_as_uint(Wp[(mtw * 16 + q + 8) * 36 + kc8 + r    ]);
            a[2] = __float_as_uint(Wp[(mtw * 16 + q    ) * 36 + kc8 + r + 4]);
            a[3] = __float_as_uint(Wp[(mtw * 16 + q + 8) * 36 + kc8 + r + 4]);
            #pragma unroll
            for (int nt = 0; nt < 4; nt++) {
                const int nc = nhw * 32 + nt * 8 + q;
                uint32_t bb[2];
                bb[0] = __float_as_uint(Xp[(kc8 + r    ) * 72 + nc]);
                bb[1] = __float_as_uint(Xp[(kc8 + r + 4) * 72 + nc]);
                mma_tf32(acc[nt], a, bb);
            }
        }
        __syncthreads();
    }

    float* Ts = smf;   // [n*68 + i]  (aliases stage memory; mainloop done)
    {
        const float blo = bias[i0 + mtw * 16 + q];
        const float bhi = bias[i0 + mtw * 16 + q + 8];
        #pragma unroll
        for (int nt = 0; nt < 4; nt++) {
            const int nb = nhw * 32 + nt * 8 + 2 * r;
            Ts[(nb    ) * 68 + mtw * 16 + q    ] = acc[nt][0] + blo;
            Ts[(nb + 1) * 68 + mtw * 16 + q    ] = acc[nt][1] + blo;
            Ts[(nb    ) * 68 + mtw * 16 + q + 8] = acc[nt][2] + bhi;
            Ts[(nb + 1) * 68 + mtw * 16 + q + 8] = acc[nt][3] + bhi;
        }
    }
    __syncthreads();

    const size_t nt64 = n0 >> 6;
    if (MODE == 0) {
        uint32_t* qout = (uint32_t*)out;
        #pragma unroll
        for (int k2 = 0; k2 < 2; k2++) {
            int p = w + 8 * k2;
            int mt = p >> 2, kcl = p & 3;
            int row = mt * 16 + q;
            int col = kcl * 16 + 2 * r;
            uint32_t u0 = pack_bf16(Ts[row * 68 + col],     Ts[row * 68 + col + 1]);
            uint32_t u1 = pack_bf16(Ts[(row + 8) * 68 + col], Ts[(row + 8) * 68 + col + 1]);
            uint32_t u2 = pack_bf16(Ts[row * 68 + col + 8], Ts[row * 68 + col + 9]);
            uint32_t u3 = pack_bf16(Ts[(row + 8) * 68 + col + 8], Ts[(row + 8) * 68 + col + 9]);
            size_t idx = ((((size_t)b * NT64 + nt64) * 4 + mt) * 8 + (i0 >> 4) + kcl) * 128
                         + l * 4;
            *(uint4*)&qout[idx] = make_uint4(u0, u1, u2, u3);
        }
    } else if (MODE == 1) {
        uint32_t* kout = (uint32_t*)out;
        #pragma unroll
        for (int k2 = 0; k2 < 4; k2++) {
            int p = w + 8 * k2;
            int ntl = p >> 2, kcl = p & 3;
            int n = ntl * 8 + q;
            int col = kcl * 16 + 2 * r;
            uint32_t u0 = pack_bf16(Ts[n * 68 + col],     Ts[n * 68 + col + 1]);
            uint32_t u1 = pack_bf16(Ts[n * 68 + col + 8], Ts[n * 68 + col + 9]);
            size_t idx = ((((size_t)b * NT64 + nt64) * 8 + (i0 >> 4) + kcl) * 4
                          + (ntl >> 1)) * 128 + l * 4 + (ntl & 1) * 2;
            *(uint2*)&kout[idx] = make_uint2(u0, u1);
        }
    } else {
        uint32_t* vout = (uint32_t*)out;
        #pragma unroll
        for (int k2 = 0; k2 < 8; k2++) {
            int pos = w + 8 * k2;
            int ntl = pos >> 3;
            int kc2 = (pos >> 1) & 3;
            int j   = pos & 1;
            int cc = ntl * 8 + q;
            int tt = kc2 * 16 + 2 * r + 8 * j;
            uint32_t v = pack_bf16(Ts[tt * 68 + cc], Ts[(tt + 1) * 68 + cc]);
            size_t idx = ((((size_t)b * NT64 + nt64) * 4 + kc2) * 16
                          + (i0 >> 4) + (ntl >> 1)) * 128
                         + l * 4 + (ntl & 1) * 2 + j;
            vout[idx] = v;
        }
    }
}

// ---------------------------------------------------------------------------
extern "C" void kernel_launch(void* const* d_in, const int* in_sizes, int n_in,
                              void* d_out, int out_size)
{
    const float* x_main  = (const float*)d_in[0];
    const float* x_guide = (const float*)d_in[1];
    const float* wq = (const float*)d_in[2];
    const float* bq = (const float*)d_in[3];
    const float* wk = (const float*)d_in[4];
    const float* bk = (const float*)d_in[5];
    const float* wv = (const float*)d_in[6];
    const float* bv = (const float*)d_in[7];
    const float* wo = (const float*)d_in[8];
    const float* bo = (const float*)d_in[9];
    const float* bng = (const float*)d_in[10];
    const float* bnb = (const float*)d_in[11];
    const float* bnm = (const float*)d_in[12];
    const float* bnv = (const float*)d_in[13];
    const float* gamma = (const float*)d_in[14];
    float* out = (float*)d_out;

    void *qf, *kf, *vf, *wof;
    cudaGetSymbolAddress(&qf, g_Qf);
    cudaGetSymbolAddress(&kf, g_Kf);
    cudaGetSymbolAddress(&vf, g_Vf);
    cudaGetSymbolAddress(&wof, g_Wof);

    const int GEMM_SMEM = 36864;

    // Wo -> bf16 A-frags (tiny, independent)
    rse_wo_prep<<<16, 512>>>(wo, (uint32_t*)wof);

    // projections -> bf16 fragment-interleaved layouts (cp.async pipelined)
    {
        dim3 gq(NSP / 64, CIQ / 64, BATCH);
        rse_proj_mma<0><<<gq, 256, GEMM_SMEM>>>(wq, bq, x_main,  (float*)qf);
        rse_proj_mma<1><<<gq, 256, GEMM_SMEM>>>(wk, bk, x_guide, (float*)kf);
        dim3 gv(NSP / 64, CCH / 64, BATCH);
        rse_proj_mma<2><<<gv, 256, GEMM_SMEM>>>(wv, bv, x_guide, (float*)vf);
    }
    // fused attention + outconv + BN + ReLU + residual
    {
        cudaFuncSetAttribute(rse_attn_fused,
                             cudaFuncAttributeMaxDynamicSharedMemorySize, ATT_SMEM);
        dim3 grid(NSP / 64, BATCH);
        rse_attn_fused<<<grid, 256, ATT_SMEM>>>(bo, bng, bnb, bnm, bnv,
                                                gamma, x_main, out);
    }
}